// round 2
// baseline (speedup 1.0000x reference)
#include <cuda_runtime.h>

#define S_LEN 2048
#define E_DIM 1024
#define NHEADS 16
#define HD 64
#define MAXROWS 2049   // nseg rows + 1 virtual row (xsum -> vtot)

// ---------------- device scratch (static, no runtime allocation) ----------------
__device__ int   g_lo, g_ns;
__device__ float g_xsum[E_DIM];
__device__ float g_vtot[E_DIM];
__device__ float g_q[MAXROWS * E_DIM];
__device__ float g_k[MAXROWS * E_DIM];
__device__ float g_v[MAXROWS * E_DIM];
__device__ float g_c[NHEADS * S_LEN];   // per-head column sums of softmax probs
__device__ float g_w0[NHEADS];          // per-head sum_i exp(-m_i)/Z_i
__device__ float g_att[E_DIM];          // mean attention output (pre-Wo)

// ---------------- K0: segment bounds ----------------
__global__ void k_bounds(const int* __restrict__ seg, const int* __restrict__ pos) {
    __shared__ int s_lo, s_cnt, s_t;
    if (threadIdx.x == 0) { s_t = seg[pos[0]]; s_lo = 0; s_cnt = 0; }
    __syncthreads();
    int t = s_t;
    int lo = 0, cnt = 0;
    for (int i = threadIdx.x; i < S_LEN; i += 256) {
        int v = seg[i];
        lo  += (v <  t);
        cnt += (v == t);
    }
    atomicAdd(&s_lo, lo);
    atomicAdd(&s_cnt, cnt);
    __syncthreads();
    if (threadIdx.x == 0) { g_lo = s_lo; g_ns = s_cnt; }
}

// ---------------- K0b: zero the scratch regions actually used this run ----------------
__global__ void k_zero(float* __restrict__ dout) {
    int ns = g_ns;
    long n3 = (long)(ns + 1) * E_DIM;
    long total = 3 * n3 + E_DIM /*xsum*/ + E_DIM /*vtot*/ + (long)NHEADS * S_LEN /*c*/
                 + NHEADS /*w0*/ + E_DIM /*dout*/;
    long stride = (long)gridDim.x * blockDim.x;
    for (long i = (long)blockIdx.x * blockDim.x + threadIdx.x; i < total; i += stride) {
        long t = i;
        if (t < n3) { g_q[t] = 0.f; continue; } t -= n3;
        if (t < n3) { g_k[t] = 0.f; continue; } t -= n3;
        if (t < n3) { g_v[t] = 0.f; continue; } t -= n3;
        if (t < E_DIM) { g_xsum[t] = 0.f; continue; } t -= E_DIM;
        if (t < E_DIM) { g_vtot[t] = 0.f; continue; } t -= E_DIM;
        if (t < (long)NHEADS * S_LEN) { g_c[t] = 0.f; continue; } t -= (long)NHEADS * S_LEN;
        if (t < NHEADS) { g_w0[t] = 0.f; continue; } t -= NHEADS;
        dout[t] = 0.f;
    }
}

// ---------------- K1: column sums of x (for Vtot) ----------------
__global__ void k_colsum(const float* __restrict__ x) {
    int c  = blockIdx.x * 256 + threadIdx.x;
    int r0 = blockIdx.y * 128;
    float acc = 0.f;
    for (int r = r0; r < r0 + 128; ++r) acc += x[(size_t)r * E_DIM + c];
    atomicAdd(&g_xsum[c], acc);
}

// ---------------- K2: projections  q/k/v = x[lo:lo+ns] @ W + b  (split-K) ----------------
// grid: (8 col-tiles of 128, 33 row-tiles of 64, 3 mats * 4 ksplits), 256 threads
__global__ void k_proj(const float* __restrict__ x,
                       const float* __restrict__ W0, const float* __restrict__ W1,
                       const float* __restrict__ W2,
                       const float* __restrict__ b0, const float* __restrict__ b1,
                       const float* __restrict__ b2) {
    const int KS = 4;
    int mat = blockIdx.z / KS;
    int kb  = blockIdx.z % KS;
    int ns = g_ns;
    int nrows = ns + (mat == 2 ? 1 : 0);   // mat 2 (Wv) has extra virtual row: xsum -> vtot
    int rt = blockIdx.y;
    if (rt * 64 >= nrows) return;
    int lo = g_lo;
    const float* W    = (mat == 0) ? W0 : ((mat == 1) ? W1 : W2);
    const float* bias = (mat == 0) ? b0 : ((mat == 1) ? b1 : b2);
    float* out = (mat == 0) ? g_q : ((mat == 1) ? g_k : g_v);

    __shared__ float As[64][17];
    __shared__ float Bs[16][132];

    int tid = threadIdx.x;
    int tx = tid & 31, ty = tid >> 5;   // 32 col-threads x 8 row-threads
    float acc[8][4];
#pragma unroll
    for (int u = 0; u < 8; u++)
#pragma unroll
        for (int v = 0; v < 4; v++) acc[u][v] = 0.f;

    int colbase = blockIdx.x * 128;
    int kstart = kb * 256;
    for (int k0 = kstart; k0 < kstart + 256; k0 += 16) {
        // load A tile 64x16 (segment x rows, or xsum for the virtual row)
#pragma unroll
        for (int u = 0; u < 4; u++) {
            int idx = tid + 256 * u;
            int r = idx >> 4, cc = idx & 15;
            int gr = rt * 64 + r;
            float vload = 0.f;
            if (gr < ns)                      vload = x[(size_t)(lo + gr) * E_DIM + k0 + cc];
            else if (gr == ns && mat == 2)    vload = g_xsum[k0 + cc];
            As[r][cc] = vload;
        }
        // load B tile 16x128
#pragma unroll
        for (int u = 0; u < 8; u++) {
            int idx = tid + 256 * u;
            int r = idx >> 7, cc = idx & 127;
            Bs[r][cc] = W[(size_t)(k0 + r) * E_DIM + colbase + cc];
        }
        __syncthreads();
#pragma unroll
        for (int kk = 0; kk < 16; kk++) {
            float bvals[4];
#pragma unroll
            for (int v = 0; v < 4; v++) bvals[v] = Bs[kk][tx + 32 * v];
#pragma unroll
            for (int u = 0; u < 8; u++) {
                float a = As[ty + 8 * u][kk];
#pragma unroll
                for (int v = 0; v < 4; v++) acc[u][v] += a * bvals[v];
            }
        }
        __syncthreads();
    }
#pragma unroll
    for (int u = 0; u < 8; u++) {
        int gr = rt * 64 + ty + 8 * u;
        if (gr >= nrows) continue;
#pragma unroll
        for (int v = 0; v < 4; v++) {
            int gc = colbase + tx + 32 * v;
            float val = acc[u][v];
            if (gr == ns && mat == 2) {
                if (kb == 0) val += (float)S_LEN * bias[gc];
                atomicAdd(&g_vtot[gc], val);
            } else {
                if (kb == 0) val += bias[gc];
                atomicAdd(&out[(size_t)gr * E_DIM + gc], val);
            }
        }
    }
}

// ---------------- K3: per-head softmax column sums ----------------
// grid (16 heads, 8 row-blocks), 256 threads (8 warps, warp per row)
__global__ void k_attn() {
    const int JT = 160;  // k-chunk rows cached in smem
    int h  = blockIdx.x;
    int rb = blockIdx.y;
    int ns = g_ns;
    int tid = threadIdx.x;
    int w = tid >> 5, lane = tid & 31;
    const float* qh = g_q + h * HD;
    const float* kh = g_k + h * HD;

    __shared__ float kbuf[JT][65];
    __shared__ float qr[8][64];
    __shared__ int s_loaded;
    if (tid == 0) s_loaded = -1;
    __syncthreads();

    int nchunks = (ns + JT - 1) / JT;
    int ngroups = (ns + 63) / 64;
    int zc = S_LEN - ns;

    for (int g = 0; g < ngroups; ++g) {
        int i = rb * 8 + w + 64 * g;
        bool active = (i < ns);
        if (active) {
            qr[w][lane]      = qh[(size_t)i * E_DIM + lane];
            qr[w][lane + 32] = qh[(size_t)i * E_DIM + lane + 32];
            __syncwarp();
        }
        // ---- pass 1: online max / sum-exp over in-segment scores ----
        float m = -1e30f, Z = 0.f;
        for (int c = 0; c < nchunks; c++) {
            int c0 = c * JT;
            int cl = min(JT, ns - c0);
            if (s_loaded != c) {
                __syncthreads();
                for (int idx = tid; idx < cl * HD; idx += 256)
                    kbuf[idx >> 6][idx & 63] = kh[(size_t)(c0 + (idx >> 6)) * E_DIM + (idx & 63)];
                if (tid == 0) s_loaded = c;
                __syncthreads();
            }
            if (active) {
                for (int j = lane; j < cl; j += 32) {
                    float s0 = 0, s1 = 0, s2 = 0, s3 = 0;
#pragma unroll
                    for (int dd = 0; dd < 64; dd += 4) {
                        s0 += qr[w][dd]     * kbuf[j][dd];
                        s1 += qr[w][dd + 1] * kbuf[j][dd + 1];
                        s2 += qr[w][dd + 2] * kbuf[j][dd + 2];
                        s3 += qr[w][dd + 3] * kbuf[j][dd + 3];
                    }
                    float s = (s0 + s1) + (s2 + s3);
                    float mn = fmaxf(m, s);
                    Z = Z * __expf(m - mn) + __expf(s - mn);
                    m = mn;
                }
            }
        }
        float mrow = 0.f, invZ = 0.f;
        if (active) {
            mrow = m;
#pragma unroll
            for (int off = 16; off > 0; off >>= 1)
                mrow = fmaxf(mrow, __shfl_xor_sync(0xffffffffu, mrow, off));
            if (zc > 0) mrow = fmaxf(mrow, 0.f);   // masked entries are ZERO, not -inf
            float z = Z * __expf(m - mrow);
#pragma unroll
            for (int off = 16; off > 0; off >>= 1)
                z += __shfl_xor_sync(0xffffffffu, z, off);
            z += (float)zc * __expf(-mrow);        // (S - ns) zero-score entries
            invZ = 1.f / z;
        }
        // ---- pass 2: accumulate column sums c_j ----
        for (int c = 0; c < nchunks; c++) {
            int c0 = c * JT;
            int cl = min(JT, ns - c0);
            if (s_loaded != c) {
                __syncthreads();
                for (int idx = tid; idx < cl * HD; idx += 256)
                    kbuf[idx >> 6][idx & 63] = kh[(size_t)(c0 + (idx >> 6)) * E_DIM + (idx & 63)];
                if (tid == 0) s_loaded = c;
                __syncthreads();
            }
            if (active) {
                for (int j = lane; j < cl; j += 32) {
                    float s0 = 0, s1 = 0, s2 = 0, s3 = 0;
#pragma unroll
                    for (int dd = 0; dd < 64; dd += 4) {
                        s0 += qr[w][dd]     * kbuf[j][dd];
                        s1 += qr[w][dd + 1] * kbuf[j][dd + 1];
                        s2 += qr[w][dd + 2] * kbuf[j][dd + 2];
                        s3 += qr[w][dd + 3] * kbuf[j][dd + 3];
                    }
                    float s = (s0 + s1) + (s2 + s3);
                    atomicAdd(&g_c[h * S_LEN + c0 + j], __expf(s - mrow) * invZ);
                }
            }
        }
        if (active && lane == 0)
            atomicAdd(&g_w0[h], __expf(-mrow) * invZ);
    }
}

// ---------------- K3b: per-head weighted V column-sum -> mean attention output ----------------
// out_mean[h,:] = (1/ns) [ sum_j (c_j - w0sum) v_j + w0sum * vtot ]
__global__ void k_comb() {
    int h  = blockIdx.x;
    int dd = threadIdx.x;   // 0..63
    int ns = g_ns;
    float w0s = g_w0[h];
    float acc = 0.f;
    for (int j = 0; j < ns; ++j)
        acc += (g_c[h * S_LEN + j] - w0s) * g_v[(size_t)j * E_DIM + h * HD + dd];
    acc += w0s * g_vtot[h * HD + dd];
    g_att[h * HD + dd] = acc / (float)ns;
}

// ---------------- K4: final vecmat  out = att @ Wo + bo  (split-K) ----------------
__global__ void k_out(const float* __restrict__ Wo, const float* __restrict__ bo,
                      float* __restrict__ dout) {
    int c  = blockIdx.x * 256 + threadIdx.x;
    int k0 = blockIdx.y * 32;
    float acc = (blockIdx.y == 0) ? bo[c] : 0.f;
#pragma unroll
    for (int kk = 0; kk < 32; kk++)
        acc += g_att[k0 + kk] * Wo[(size_t)(k0 + kk) * E_DIM + c];
    atomicAdd(&dout[c], acc);
}

// ---------------- launch ----------------
extern "C" void kernel_launch(void* const* d_in, const int* in_sizes, int n_in,
                              void* d_out, int out_size) {
    const float* x  = (const float*)d_in[0];
    const int*   seg = (const int*)d_in[1];
    const int*   pos = (const int*)d_in[2];
    const float* Wq = (const float*)d_in[3];
    const float* bq = (const float*)d_in[4];
    const float* Wk = (const float*)d_in[5];
    const float* bk = (const float*)d_in[6];
    const float* Wv = (const float*)d_in[7];
    const float* bv = (const float*)d_in[8];
    const float* Wo = (const float*)d_in[9];
    const float* bo = (const float*)d_in[10];
    float* out = (float*)d_out;

    k_bounds<<<1, 256>>>(seg, pos);
    k_zero<<<128, 256>>>(out);
    k_colsum<<<dim3(4, 16), 256>>>(x);
    k_proj<<<dim3(8, 33, 12), 256>>>(x, Wq, Wk, Wv, bq, bk, bv);
    k_attn<<<dim3(NHEADS, 8), 256>>>();
    k_comb<<<NHEADS, 64>>>();
    k_out<<<dim3(4, 32), 256>>>(Wo, bo, out);
}

// round 3
// speedup vs baseline: 1.2408x; 1.2408x over previous
#include <cuda_runtime.h>

#define S_LEN   2048
#define E_DIM   1024
#define NHEADS  16
#define HD      64
#define MAXR    2049   // ns rows + 1 virtual row (xsum -> vtot)
#define KSPLIT  16     // proj K-splits (64 k each)
#define RCAP    128    // rows covered by the fast partial-buffer path
#define XS      32     // colsum row splits

// ---------------- device scratch (static, no runtime allocation) ----------------
__device__ int   g_lo, g_ns;
__device__ float g_xsump[XS][E_DIM];
__device__ float g_qp[KSPLIT][RCAP * E_DIM];
__device__ float g_kp[KSPLIT][RCAP * E_DIM];
__device__ float g_vp[KSPLIT][RCAP * E_DIM];
__device__ float g_q[MAXR * E_DIM];
__device__ float g_k[MAXR * E_DIM];
__device__ float g_v[MAXR * E_DIM];   // row ns = vtot
__device__ float g_att[E_DIM];

// ---------------- f32x2 packed helpers ----------------
__device__ __forceinline__ unsigned long long pk2(float lo, float hi) {
    unsigned long long r;
    asm("mov.b64 %0, {%1,%2};" : "=l"(r) : "f"(lo), "f"(hi));
    return r;
}
__device__ __forceinline__ void upk2(unsigned long long v, float& lo, float& hi) {
    asm("mov.b64 {%0,%1}, %2;" : "=f"(lo), "=f"(hi) : "l"(v));
}
__device__ __forceinline__ void ffma2(unsigned long long& d, unsigned long long a,
                                      unsigned long long b) {
    asm("fma.rn.f32x2 %0, %1, %2, %0;" : "+l"(d) : "l"(a), "l"(b));
}

// ---------------- K0: segment bounds ----------------
__global__ void k_bounds(const int* __restrict__ seg, const int* __restrict__ pos) {
    __shared__ int s_lo, s_cnt, s_t;
    if (threadIdx.x == 0) { s_t = seg[pos[0]]; s_lo = 0; s_cnt = 0; }
    __syncthreads();
    int t = s_t;
    int lo = 0, cnt = 0;
    for (int i = threadIdx.x; i < S_LEN; i += 256) {
        int v = seg[i];
        lo  += (v <  t);
        cnt += (v == t);
    }
    atomicAdd(&s_lo, lo);
    atomicAdd(&s_cnt, cnt);
    __syncthreads();
    if (threadIdx.x == 0) { g_lo = s_lo; g_ns = s_cnt; }
}

// ---------------- K1: partial column sums of x ----------------
__global__ void k_colsum(const float* __restrict__ x) {
    int c  = blockIdx.x * 256 + threadIdx.x;
    int r0 = blockIdx.y * 64;
    float a = 0.f;
#pragma unroll 8
    for (int r = r0; r < r0 + 64; ++r) a += x[(size_t)r * E_DIM + c];
    g_xsump[blockIdx.y][c] = a;
}

// ---------------- K2: projections (split-K, partial buffers, FFMA2) ----------------
// grid (8 coltiles x128, KSPLIT=16, 3 mats) = 384 blocks, 256 threads
__global__ void __launch_bounds__(256) k_proj(
    const float* __restrict__ x,
    const float* __restrict__ W0, const float* __restrict__ W1,
    const float* __restrict__ W2,
    const float* __restrict__ b0, const float* __restrict__ b1,
    const float* __restrict__ b2) {
    int mat = blockIdx.z;
    int kb  = blockIdx.y;
    int ns = g_ns, lo = g_lo;
    int nrows = ns + (mat == 2 ? 1 : 0);
    const float* W    = (mat == 0) ? W0 : ((mat == 1) ? W1 : W2);
    const float* bias = (mat == 0) ? b0 : ((mat == 1) ? b1 : b2);
    float* partial = (mat == 0) ? g_qp[kb] : ((mat == 1) ? g_kp[kb] : g_vp[kb]);
    float* dense   = (mat == 0) ? g_q : ((mat == 1) ? g_k : g_v);
    int colbase = blockIdx.x * 128;
    int tid = threadIdx.x;
    int tx = tid & 15, ty = tid >> 4;

    __shared__ float As[16][64];    // [k][row]
    __shared__ float Bs[16][128];   // [k][col]

    // loader mappings
    int ra = tid >> 2, kq = (tid & 3) << 2;   // A: row ra, 4 k's starting kq
    int kr = ty, colb = tx * 8;               // B: k-row kr, 8 cols starting colb

    int rtmax = (nrows + 63) >> 6;
    for (int rt = 0; rt < rtmax; rt++) {
        bool densepath = (rt * 64 >= RCAP);
        if (densepath && kb != 0) break;      // overflow rows: only kb==0, full K
        int kbase = densepath ? 0 : kb * 64;
        int NC    = densepath ? 64 : 4;       // 16-wide K chunks
        int gr_a  = rt * 64 + ra;

        unsigned long long acc[4][4];
#pragma unroll
        for (int r = 0; r < 4; r++)
#pragma unroll
            for (int p = 0; p < 4; p++) acc[r][p] = 0ULL;

        float4 aReg, bReg0, bReg1;
        {   // prefetch chunk 0
            int kidx = kbase + kq;
            aReg = make_float4(0.f, 0.f, 0.f, 0.f);
            if (gr_a < ns) {
                aReg = *(const float4*)&x[(size_t)(lo + gr_a) * E_DIM + kidx];
            } else if (gr_a == ns && mat == 2) {
                float s0 = 0, s1 = 0, s2 = 0, s3 = 0;
#pragma unroll
                for (int p = 0; p < XS; p++) {
                    s0 += g_xsump[p][kidx];     s1 += g_xsump[p][kidx + 1];
                    s2 += g_xsump[p][kidx + 2]; s3 += g_xsump[p][kidx + 3];
                }
                aReg = make_float4(s0, s1, s2, s3);
            }
            const float* wp = &W[(size_t)(kbase + kr) * E_DIM + colbase + colb];
            bReg0 = *(const float4*)wp;
            bReg1 = *(const float4*)(wp + 4);
        }

        for (int c = 0; c < NC; c++) {
            As[kq + 0][ra] = aReg.x; As[kq + 1][ra] = aReg.y;
            As[kq + 2][ra] = aReg.z; As[kq + 3][ra] = aReg.w;
            *(float4*)&Bs[kr][colb]     = bReg0;
            *(float4*)&Bs[kr][colb + 4] = bReg1;
            __syncthreads();
            if (c + 1 < NC) {
                int kidx = kbase + (c + 1) * 16 + kq;
                aReg = make_float4(0.f, 0.f, 0.f, 0.f);
                if (gr_a < ns) {
                    aReg = *(const float4*)&x[(size_t)(lo + gr_a) * E_DIM + kidx];
                } else if (gr_a == ns && mat == 2) {
                    float s0 = 0, s1 = 0, s2 = 0, s3 = 0;
#pragma unroll
                    for (int p = 0; p < XS; p++) {
                        s0 += g_xsump[p][kidx];     s1 += g_xsump[p][kidx + 1];
                        s2 += g_xsump[p][kidx + 2]; s3 += g_xsump[p][kidx + 3];
                    }
                    aReg = make_float4(s0, s1, s2, s3);
                }
                const float* wp = &W[(size_t)(kbase + (c + 1) * 16 + kr) * E_DIM
                                     + colbase + colb];
                bReg0 = *(const float4*)wp;
                bReg1 = *(const float4*)(wp + 4);
            }
#pragma unroll
            for (int kk = 0; kk < 16; kk++) {
                float4 av = *(float4*)&As[kk][ty * 4];
                unsigned long long a0 = pk2(av.x, av.x), a1 = pk2(av.y, av.y);
                unsigned long long a2 = pk2(av.z, av.z), a3 = pk2(av.w, av.w);
                float bv[8];
#pragma unroll
                for (int cc = 0; cc < 8; cc++) bv[cc] = Bs[kk][tx + 16 * cc];
#pragma unroll
                for (int p = 0; p < 4; p++) {
                    unsigned long long bp = pk2(bv[2 * p], bv[2 * p + 1]);
                    ffma2(acc[0][p], a0, bp);
                    ffma2(acc[1][p], a1, bp);
                    ffma2(acc[2][p], a2, bp);
                    ffma2(acc[3][p], a3, bp);
                }
            }
            __syncthreads();
        }
        // epilogue
        bool addBias = (kb == 0) || densepath;
#pragma unroll
        for (int r = 0; r < 4; r++) {
            int gr = rt * 64 + ty * 4 + r;
            if (gr >= nrows) continue;
#pragma unroll
            for (int p = 0; p < 4; p++) {
                float v0, v1;
                upk2(acc[r][p], v0, v1);
                int c0 = colbase + tx + 16 * (2 * p);
                int c1 = colbase + tx + 16 * (2 * p + 1);
                if (addBias) {
                    float s = (gr == ns && mat == 2) ? (float)S_LEN : 1.f;
                    v0 += s * bias[c0];
                    v1 += s * bias[c1];
                }
                if (densepath) {
                    dense[(size_t)gr * E_DIM + c0] = v0;
                    dense[(size_t)gr * E_DIM + c1] = v1;
                } else {
                    partial[(size_t)gr * E_DIM + c0] = v0;
                    partial[(size_t)gr * E_DIM + c1] = v1;
                }
            }
        }
    }
}

// ---------------- K2b: sum split-K partials into dense q/k/v ----------------
__global__ void k_reduce() {
    int ns = g_ns;
    int rows = min(ns + 1, RCAP);
    int total = rows * E_DIM;
    int stride = gridDim.x * blockDim.x;
    for (int i = blockIdx.x * blockDim.x + threadIdx.x; i < total; i += stride) {
        float sq = 0.f, sk = 0.f, sv = 0.f;
#pragma unroll
        for (int p = 0; p < KSPLIT; p++) {
            sq += g_qp[p][i];
            sk += g_kp[p][i];
            sv += g_vp[p][i];
        }
        g_q[i] = sq; g_k[i] = sk; g_v[i] = sv;
    }
}

// ---------------- K3: per-head softmax column sums + weighted V sum ----------------
// one block per head, 256 threads, smem accumulation (no global atomics)
__global__ void __launch_bounds__(256) k_attn(float* __restrict__ dout) {
    const int JT = 128;
    int h = blockIdx.x, ns = g_ns;
    int tid = threadIdx.x, w = tid >> 5, lane = tid & 31;
    const float* qh = g_q + h * HD;
    const float* kh = g_k + h * HD;

    __shared__ float kbuf[JT][65];
    __shared__ float qr[8][64];
    __shared__ float c_acc[S_LEN];
    __shared__ float red[4][64];
    __shared__ float w0s;
    __shared__ int s_loaded;
    if (tid == 0) { s_loaded = -1; w0s = 0.f; }
    for (int i = tid; i < ns; i += 256) c_acc[i] = 0.f;
    __syncthreads();

    int nchunks = (ns + JT - 1) / JT;
    int ngroups = (ns + 7) / 8;
    int zc = S_LEN - ns;

    for (int g = 0; g < ngroups; ++g) {
        int i = g * 8 + w;
        bool active = (i < ns);
        if (active) {
            qr[w][lane]      = qh[(size_t)i * E_DIM + lane];
            qr[w][lane + 32] = qh[(size_t)i * E_DIM + lane + 32];
            __syncwarp();
        }
        // pass 1: online max / sum-exp
        float m = -1e30f, Z = 0.f;
        for (int c = 0; c < nchunks; c++) {
            int c0 = c * JT;
            int cl = min(JT, ns - c0);
            if (s_loaded != c) {
                __syncthreads();
                for (int idx = tid; idx < cl * HD; idx += 256)
                    kbuf[idx >> 6][idx & 63] =
                        kh[(size_t)(c0 + (idx >> 6)) * E_DIM + (idx & 63)];
                if (tid == 0) s_loaded = c;
                __syncthreads();
            }
            if (active) {
                for (int j = lane; j < cl; j += 32) {
                    float s0 = 0, s1 = 0, s2 = 0, s3 = 0;
#pragma unroll
                    for (int dd = 0; dd < 64; dd += 4) {
                        s0 += qr[w][dd]     * kbuf[j][dd];
                        s1 += qr[w][dd + 1] * kbuf[j][dd + 1];
                        s2 += qr[w][dd + 2] * kbuf[j][dd + 2];
                        s3 += qr[w][dd + 3] * kbuf[j][dd + 3];
                    }
                    float s = (s0 + s1) + (s2 + s3);
                    float mn = fmaxf(m, s);
                    Z = Z * __expf(m - mn) + __expf(s - mn);
                    m = mn;
                }
            }
        }
        float mrow = 0.f, invZ = 0.f;
        if (active) {
            mrow = m;
#pragma unroll
            for (int o = 16; o > 0; o >>= 1)
                mrow = fmaxf(mrow, __shfl_xor_sync(0xffffffffu, mrow, o));
            if (zc > 0) mrow = fmaxf(mrow, 0.f);    // masked entries are ZERO
            float z = Z * __expf(m - mrow);
#pragma unroll
            for (int o = 16; o > 0; o >>= 1)
                z += __shfl_xor_sync(0xffffffffu, z, o);
            z += (float)zc * __expf(-mrow);
            invZ = 1.f / z;
        }
        // pass 2: accumulate column sums into smem
        for (int c = 0; c < nchunks; c++) {
            int c0 = c * JT;
            int cl = min(JT, ns - c0);
            if (s_loaded != c) {
                __syncthreads();
                for (int idx = tid; idx < cl * HD; idx += 256)
                    kbuf[idx >> 6][idx & 63] =
                        kh[(size_t)(c0 + (idx >> 6)) * E_DIM + (idx & 63)];
                if (tid == 0) s_loaded = c;
                __syncthreads();
            }
            if (active) {
                for (int j = lane; j < cl; j += 32) {
                    float s0 = 0, s1 = 0, s2 = 0, s3 = 0;
#pragma unroll
                    for (int dd = 0; dd < 64; dd += 4) {
                        s0 += qr[w][dd]     * kbuf[j][dd];
                        s1 += qr[w][dd + 1] * kbuf[j][dd + 1];
                        s2 += qr[w][dd + 2] * kbuf[j][dd + 2];
                        s3 += qr[w][dd + 3] * kbuf[j][dd + 3];
                    }
                    float s = (s0 + s1) + (s2 + s3);
                    atomicAdd(&c_acc[c0 + j], __expf(s - mrow) * invZ);
                }
            }
        }
        if (active && lane == 0) atomicAdd(&w0s, __expf(-mrow) * invZ);
    }
    __syncthreads();

    // weighted V column-sum -> mean attention output (fused old k_comb)
    int d = tid & 63, grp = tid >> 6;
    float w0 = w0s;
    float acc = 0.f;
    for (int j = grp; j < ns; j += 4)
        acc += (c_acc[j] - w0) * g_v[(size_t)j * E_DIM + h * HD + d];
    red[grp][d] = acc;
    __syncthreads();
    if (tid < 64) {
        float a = red[0][d] + red[1][d] + red[2][d] + red[3][d]
                + w0 * g_v[(size_t)ns * E_DIM + h * HD + d];   // vtot row
        g_att[h * HD + d] = a / (float)ns;
        dout[h * HD + d] = 0.f;                                // zero for k_out atomics
    }
}

// ---------------- K4: final vecmat out = att @ Wo + bo (split-K) ----------------
__global__ void k_out(const float* __restrict__ Wo, const float* __restrict__ bo,
                      float* __restrict__ dout) {
    int c  = blockIdx.x * 256 + threadIdx.x;
    int k0 = blockIdx.y * 64;
    __shared__ float a_s[64];
    if (threadIdx.x < 64) a_s[threadIdx.x] = g_att[k0 + threadIdx.x];
    __syncthreads();
    float acc = (blockIdx.y == 0) ? bo[c] : 0.f;
#pragma unroll 16
    for (int kk = 0; kk < 64; kk++)
        acc += a_s[kk] * Wo[(size_t)(k0 + kk) * E_DIM + c];
    atomicAdd(&dout[c], acc);
}

// ---------------- launch ----------------
extern "C" void kernel_launch(void* const* d_in, const int* in_sizes, int n_in,
                              void* d_out, int out_size) {
    const float* x   = (const float*)d_in[0];
    const int*   seg = (const int*)d_in[1];
    const int*   pos = (const int*)d_in[2];
    const float* Wq = (const float*)d_in[3];
    const float* bq = (const float*)d_in[4];
    const float* Wk = (const float*)d_in[5];
    const float* bk = (const float*)d_in[6];
    const float* Wv = (const float*)d_in[7];
    const float* bv = (const float*)d_in[8];
    const float* Wo = (const float*)d_in[9];
    const float* bo = (const float*)d_in[10];
    float* out = (float*)d_out;

    k_bounds<<<1, 256>>>(seg, pos);
    k_colsum<<<dim3(4, XS), 256>>>(x);
    k_proj<<<dim3(8, KSPLIT, 3), 256>>>(x, Wq, Wk, Wv, bq, bk, bv);
    k_reduce<<<128, 256>>>();
    k_attn<<<NHEADS, 256>>>(out);
    k_out<<<dim3(4, 16), 256>>>(Wo, bo, out);
}

// round 4
// speedup vs baseline: 1.9038x; 1.5343x over previous
#include <cuda_runtime.h>

#define S_LEN   2048
#define E_DIM   1024
#define NHEADS  16
#define HD      64
#define MAXR    2049   // ns rows + 1 virtual row (xsum -> vtot)
#define KSPLIT  16     // proj K-splits (64 k each)
#define RCAP    128    // rows covered by the split partial-buffer path
#define XS      64     // colsum row splits

// ---------------- device scratch (static, no runtime allocation) ----------------
__device__ int   g_lo, g_ns;
__device__ float g_xsum[E_DIM];
__device__ float g_qp[KSPLIT][RCAP * E_DIM];
__device__ float g_kp[KSPLIT][RCAP * E_DIM];
__device__ float g_vp[KSPLIT][RCAP * E_DIM];
__device__ float g_q[MAXR * E_DIM];
__device__ float g_k[MAXR * E_DIM];
__device__ float g_v[MAXR * E_DIM];   // row ns = vtot
__device__ float g_att[E_DIM];

// ---------------- f32x2 packed helpers ----------------
__device__ __forceinline__ unsigned long long pk2(float lo, float hi) {
    unsigned long long r;
    asm("mov.b64 %0, {%1,%2};" : "=l"(r) : "f"(lo), "f"(hi));
    return r;
}
__device__ __forceinline__ void upk2(unsigned long long v, float& lo, float& hi) {
    asm("mov.b64 {%0,%1}, %2;" : "=f"(lo), "=f"(hi) : "l"(v));
}
__device__ __forceinline__ void ffma2(unsigned long long& d, unsigned long long a,
                                      unsigned long long b) {
    asm("fma.rn.f32x2 %0, %1, %2, %0;" : "+l"(d) : "l"(a), "l"(b));
}

// ---------------- K0: segment bounds + zero g_xsum ----------------
__global__ void k_bounds(const int* __restrict__ seg, const int* __restrict__ pos) {
    __shared__ int s_lo, s_cnt, s_t;
    if (threadIdx.x == 0) { s_t = seg[pos[0]]; s_lo = 0; s_cnt = 0; }
    __syncthreads();
    int t = s_t;
    int lo = 0, cnt = 0;
    for (int i = threadIdx.x; i < S_LEN; i += 256) {
        int v = seg[i];
        lo  += (v <  t);
        cnt += (v == t);
    }
    atomicAdd(&s_lo, lo);
    atomicAdd(&s_cnt, cnt);
    for (int i = threadIdx.x; i < E_DIM; i += 256) g_xsum[i] = 0.f;
    __syncthreads();
    if (threadIdx.x == 0) { g_lo = s_lo; g_ns = s_cnt; }
}

// ---------------- K1: column sums of x (atomic partials) ----------------
__global__ void k_colsum(const float* __restrict__ x) {
    int c  = blockIdx.x * 256 + threadIdx.x;
    int r0 = blockIdx.y * (S_LEN / XS);
    float a = 0.f;
#pragma unroll 8
    for (int r = r0; r < r0 + S_LEN / XS; ++r) a += x[(size_t)r * E_DIM + c];
    atomicAdd(&g_xsum[c], a);
}

// ---------------- proj tile worker (M = 16*R, N = 128, 16-wide K chunks) ----------------
template<int R>
__device__ __forceinline__ void proj_tile(
    const float* __restrict__ x, const float* __restrict__ W,
    const float* __restrict__ bias, float* __restrict__ outp,
    int lo, int ns, int nrows, int mat, int rowbase, int kbase, int nchunk,
    bool addBias, float (*As)[128], float (*Bs)[128], int colbase)
{
    int tid = threadIdx.x;
    int tx = tid & 15, ty = tid >> 4;
    int arow = (R == 4) ? (tid >> 2) : (tid >> 1);
    int aks  = (R == 4) ? ((tid & 3) << 2) : ((tid & 1) << 3);
    int gr_a = rowbase + arow;
    int bkr = ty, bcol = tx * 8;

    auto ldA = [&](int kidx) -> float4 {
        if (gr_a < ns)                 return *(const float4*)&x[(size_t)(lo + gr_a) * E_DIM + kidx];
        if (gr_a == ns && mat == 2)    return *(const float4*)&g_xsum[kidx];
        return make_float4(0.f, 0.f, 0.f, 0.f);
    };

    unsigned long long acc[R][4];
#pragma unroll
    for (int r = 0; r < R; r++)
#pragma unroll
        for (int p = 0; p < 4; p++) acc[r][p] = 0ULL;

    float4 a0, a1, b0, b1;
    {   // prefetch chunk 0
        int kidx = kbase + aks;
        a0 = ldA(kidx);
        if (R == 8) a1 = ldA(kidx + 4);
        const float* wp = &W[(size_t)(kbase + bkr) * E_DIM + colbase + bcol];
        b0 = *(const float4*)wp;
        b1 = *(const float4*)(wp + 4);
    }

    for (int c = 0; c < nchunk; c++) {
        As[aks + 0][arow] = a0.x; As[aks + 1][arow] = a0.y;
        As[aks + 2][arow] = a0.z; As[aks + 3][arow] = a0.w;
        if (R == 8) {
            As[aks + 4][arow] = a1.x; As[aks + 5][arow] = a1.y;
            As[aks + 6][arow] = a1.z; As[aks + 7][arow] = a1.w;
        }
        *(float4*)&Bs[bkr][bcol]     = b0;
        *(float4*)&Bs[bkr][bcol + 4] = b1;
        __syncthreads();
        if (c + 1 < nchunk) {
            int kidx = kbase + (c + 1) * 16 + aks;
            a0 = ldA(kidx);
            if (R == 8) a1 = ldA(kidx + 4);
            const float* wp = &W[(size_t)(kbase + (c + 1) * 16 + bkr) * E_DIM + colbase + bcol];
            b0 = *(const float4*)wp;
            b1 = *(const float4*)(wp + 4);
        }
#pragma unroll
        for (int kk = 0; kk < 16; kk++) {
            float bv[8];
#pragma unroll
            for (int cc = 0; cc < 8; cc++) bv[cc] = Bs[kk][tx + 16 * cc];
            unsigned long long bp[4];
#pragma unroll
            for (int p = 0; p < 4; p++) bp[p] = pk2(bv[2 * p], bv[2 * p + 1]);
#pragma unroll
            for (int q = 0; q < R / 4; q++) {
                float4 av = *(float4*)&As[kk][ty * R + 4 * q];
#pragma unroll
                for (int rr = 0; rr < 4; rr++) {
                    float a = (rr == 0) ? av.x : (rr == 1) ? av.y : (rr == 2) ? av.z : av.w;
                    unsigned long long ap = pk2(a, a);
#pragma unroll
                    for (int p = 0; p < 4; p++) ffma2(acc[4 * q + rr][p], ap, bp[p]);
                }
            }
        }
        __syncthreads();
    }
    // epilogue
#pragma unroll
    for (int r = 0; r < R; r++) {
        int gr = rowbase + ty * R + r;
        if (gr >= nrows) continue;
        bool virt = (gr == ns && mat == 2);
#pragma unroll
        for (int p = 0; p < 4; p++) {
            float v0, v1;
            upk2(acc[r][p], v0, v1);
            int c0 = colbase + tx + 16 * (2 * p), c1 = c0 + 16;
            if (addBias) {
                float sc = virt ? (float)S_LEN : 1.f;
                v0 += sc * bias[c0];
                v1 += sc * bias[c1];
            }
            outp[(size_t)gr * E_DIM + c0] = v0;
            outp[(size_t)gr * E_DIM + c1] = v1;
        }
    }
}

// ---------------- K2: projections (split-K into partial buffers) ----------------
// grid (8 coltiles x128, KSPLIT, 3 mats), 256 threads
__global__ void __launch_bounds__(256) k_proj(
    const float* __restrict__ x,
    const float* __restrict__ W0, const float* __restrict__ W1,
    const float* __restrict__ W2,
    const float* __restrict__ b0, const float* __restrict__ b1,
    const float* __restrict__ b2) {
    __shared__ float As[16][128];
    __shared__ float Bs[16][128];
    int mat = blockIdx.z;
    int kb  = blockIdx.y;
    int ns = g_ns, lo = g_lo;
    int nrows = ns + (mat == 2 ? 1 : 0);
    const float* W    = (mat == 0) ? W0 : ((mat == 1) ? W1 : W2);
    const float* bias = (mat == 0) ? b0 : ((mat == 1) ? b1 : b2);
    float* partial = (mat == 0) ? g_qp[kb] : ((mat == 1) ? g_kp[kb] : g_vp[kb]);
    float* dense   = (mat == 0) ? g_q : ((mat == 1) ? g_k : g_v);
    int colbase = blockIdx.x * 128;

    int rows_split = min(nrows, RCAP);
    if (rows_split <= 64)
        proj_tile<4>(x, W, bias, partial, lo, ns, rows_split, mat,
                     0, kb * 64, 4, kb == 0, As, Bs, colbase);
    else
        proj_tile<8>(x, W, bias, partial, lo, ns, rows_split, mat,
                     0, kb * 64, 4, kb == 0, As, Bs, colbase);

    // rare overflow path: rows >= RCAP computed dense (full K) by kb==0 blocks
    if (nrows > RCAP && kb == 0)
        for (int rowbase = RCAP; rowbase < nrows; rowbase += 64)
            proj_tile<4>(x, W, bias, dense, lo, ns, nrows, mat,
                         rowbase, 0, 64, true, As, Bs, colbase);
}

// ---------------- K2b: sum split-K partials into dense q/k/v ----------------
__global__ void k_reduce() {
    int ns = g_ns;
    int total = min(ns + 1, RCAP) * E_DIM;
    int i = blockIdx.x * 256 + threadIdx.x;
    if (i >= total) return;
    float sq = 0.f, sk = 0.f, sv = 0.f;
#pragma unroll
    for (int p = 0; p < KSPLIT; p++) {
        sq += g_qp[p][i];
        sk += g_kp[p][i];
        sv += g_vp[p][i];
    }
    g_q[i] = sq; g_k[i] = sk; g_v[i] = sv;
}

// ---------------- K3: per-head softmax column sums + weighted V sum ----------------
// one block per head, 512 threads (16 warps, warp per row)
__global__ void __launch_bounds__(512) k_attn(float* __restrict__ dout) {
    const int JT = 128;
    int h = blockIdx.x, ns = g_ns;
    int tid = threadIdx.x, w = tid >> 5, lane = tid & 31;
    const float* qh = g_q + h * HD;
    const float* kh = g_k + h * HD;

    __shared__ float kbuf[JT][65];
    __shared__ float qr[16][64];
    __shared__ float c_acc[S_LEN];
    __shared__ float red[8][64];
    __shared__ float w0s;
    __shared__ int s_loaded;
    if (tid == 0) { s_loaded = -1; w0s = 0.f; }
    for (int i = tid; i < ns; i += 512) c_acc[i] = 0.f;
    __syncthreads();

    int nchunks = (ns + JT - 1) / JT;
    int ngroups = (ns + 15) / 16;
    int zc = S_LEN - ns;
    bool cacheS = (ns <= 256);

    for (int g = 0; g < ngroups; ++g) {
        int i = g * 16 + w;
        bool active = (i < ns);
        if (active) {
            qr[w][lane]      = qh[(size_t)i * E_DIM + lane];
            qr[w][lane + 32] = qh[(size_t)i * E_DIM + lane + 32];
            __syncwarp();
        }
        float sreg[8];
        // pass 1: online max / sum-exp (cache scores when they fit)
        float m = -1e30f, Z = 0.f;
        for (int c = 0; c < nchunks; c++) {
            int c0 = c * JT;
            int cl = min(JT, ns - c0);
            if (s_loaded != c) {
                __syncthreads();
                for (int idx = tid; idx < cl * HD; idx += 512)
                    kbuf[idx >> 6][idx & 63] =
                        kh[(size_t)(c0 + (idx >> 6)) * E_DIM + (idx & 63)];
                if (tid == 0) s_loaded = c;
                __syncthreads();
            }
            if (active) {
                for (int j = lane; j < cl; j += 32) {
                    float s0 = 0, s1 = 0, s2 = 0, s3 = 0;
#pragma unroll
                    for (int dd = 0; dd < 64; dd += 4) {
                        s0 += qr[w][dd]     * kbuf[j][dd];
                        s1 += qr[w][dd + 1] * kbuf[j][dd + 1];
                        s2 += qr[w][dd + 2] * kbuf[j][dd + 2];
                        s3 += qr[w][dd + 3] * kbuf[j][dd + 3];
                    }
                    float s = (s0 + s1) + (s2 + s3);
                    if (cacheS) sreg[(c0 + j) >> 5] = s;
                    float mn = fmaxf(m, s);
                    Z = Z * __expf(m - mn) + __expf(s - mn);
                    m = mn;
                }
            }
        }
        float mrow = 0.f, invZ = 0.f;
        if (active) {
            mrow = m;
#pragma unroll
            for (int o = 16; o > 0; o >>= 1)
                mrow = fmaxf(mrow, __shfl_xor_sync(0xffffffffu, mrow, o));
            if (zc > 0) mrow = fmaxf(mrow, 0.f);    // masked entries are ZERO, not -inf
            float z = Z * __expf(m - mrow);
#pragma unroll
            for (int o = 16; o > 0; o >>= 1)
                z += __shfl_xor_sync(0xffffffffu, z, o);
            z += (float)zc * __expf(-mrow);
            invZ = 1.f / z;
        }
        // pass 2: column-sum accumulation
        if (cacheS) {
            if (active) {
                for (int t = 0; t * 32 < ns; t++) {
                    int jc = t * 32 + lane;
                    if (jc < ns)
                        atomicAdd(&c_acc[jc], __expf(sreg[t] - mrow) * invZ);
                }
            }
        } else {
            for (int c = 0; c < nchunks; c++) {
                int c0 = c * JT;
                int cl = min(JT, ns - c0);
                if (s_loaded != c) {
                    __syncthreads();
                    for (int idx = tid; idx < cl * HD; idx += 512)
                        kbuf[idx >> 6][idx & 63] =
                            kh[(size_t)(c0 + (idx >> 6)) * E_DIM + (idx & 63)];
                    if (tid == 0) s_loaded = c;
                    __syncthreads();
                }
                if (active) {
                    for (int j = lane; j < cl; j += 32) {
                        float s0 = 0, s1 = 0, s2 = 0, s3 = 0;
#pragma unroll
                        for (int dd = 0; dd < 64; dd += 4) {
                            s0 += qr[w][dd]     * kbuf[j][dd];
                            s1 += qr[w][dd + 1] * kbuf[j][dd + 1];
                            s2 += qr[w][dd + 2] * kbuf[j][dd + 2];
                            s3 += qr[w][dd + 3] * kbuf[j][dd + 3];
                        }
                        float s = (s0 + s1) + (s2 + s3);
                        atomicAdd(&c_acc[c0 + j], __expf(s - mrow) * invZ);
                    }
                }
            }
        }
        if (active && lane == 0) atomicAdd(&w0s, __expf(-mrow) * invZ);
    }
    __syncthreads();

    // weighted V column-sum -> mean attention output
    int d = tid & 63, grp = tid >> 6;
    float w0 = w0s;
    float acc = 0.f;
    for (int j = grp; j < ns; j += 8)
        acc += (c_acc[j] - w0) * g_v[(size_t)j * E_DIM + h * HD + d];
    red[grp][d] = acc;
    __syncthreads();
    if (tid < 64) {
        float a = red[0][d] + red[1][d] + red[2][d] + red[3][d]
                + red[4][d] + red[5][d] + red[6][d] + red[7][d]
                + w0 * g_v[(size_t)ns * E_DIM + h * HD + d];   // vtot row
        g_att[h * HD + d] = a / (float)ns;
        dout[h * HD + d] = 0.f;                                // zero for k_out atomics
    }
}

// ---------------- K4: final vecmat out = att @ Wo + bo (split-K x64) ----------------
__global__ void k_out(const float* __restrict__ Wo, const float* __restrict__ bo,
                      float* __restrict__ dout) {
    int c  = blockIdx.x * 256 + threadIdx.x;
    int k0 = blockIdx.y * 16;
    __shared__ float a_s[16];
    if (threadIdx.x < 16) a_s[threadIdx.x] = g_att[k0 + threadIdx.x];
    __syncthreads();
    float acc = (blockIdx.y == 0) ? bo[c] : 0.f;
#pragma unroll 16
    for (int kk = 0; kk < 16; kk++)
        acc += a_s[kk] * Wo[(size_t)(k0 + kk) * E_DIM + c];
    atomicAdd(&dout[c], acc);
}

// ---------------- launch ----------------
extern "C" void kernel_launch(void* const* d_in, const int* in_sizes, int n_in,
                              void* d_out, int out_size) {
    const float* x   = (const float*)d_in[0];
    const int*   seg = (const int*)d_in[1];
    const int*   pos = (const int*)d_in[2];
    const float* Wq = (const float*)d_in[3];
    const float* bq = (const float*)d_in[4];
    const float* Wk = (const float*)d_in[5];
    const float* bk = (const float*)d_in[6];
    const float* Wv = (const float*)d_in[7];
    const float* bv = (const float*)d_in[8];
    const float* Wo = (const float*)d_in[9];
    const float* bo = (const float*)d_in[10];
    float* out = (float*)d_out;

    k_bounds<<<1, 256>>>(seg, pos);
    k_colsum<<<dim3(4, XS), 256>>>(x);
    k_proj<<<dim3(8, KSPLIT, 3), 256>>>(x, Wq, Wk, Wv, bq, bk, bv);
    k_reduce<<<512, 256>>>();
    k_attn<<<NHEADS, 512>>>(out);
    k_out<<<dim3(4, 64), 256>>>(Wo, bo, out);
}